// round 1
// baseline (speedup 1.0000x reference)
#include <cuda_runtime.h>

// Problem constants
#define L 4
#define B 128
#define T 1024
#define NI 512
#define H 512
#define G 2048          // 4*H
#define BH (B*H)
#define BG (B*G)

#define NBLK 128
#define NTHR 256

// Scratch (device globals: allocation-free rule)
__device__ float g_seq[(size_t)T * BH];    // layer io sequence, (t, b, h), 256 MB
__device__ float g_part[4 * BG];           // splitK partial sums, 4 MB
__device__ unsigned long long g_arrive;
__device__ volatile unsigned long long g_release;

__device__ __forceinline__ void gsync() {
    __syncthreads();
    if (threadIdx.x == 0) {
        __threadfence();
        unsigned long long my = atomicAdd(&g_arrive, 1ULL);
        unsigned long long target = my / NBLK + 1ULL;
        if ((my % NBLK) == (NBLK - 1)) {
            __threadfence();
            g_release = target;
        } else {
            while (g_release < target) { }
        }
        __threadfence();
    }
    __syncthreads();
}

__device__ __forceinline__ float sigmoidf_fast(float x) {
    return 1.0f / (1.0f + __expf(-x));
}

__global__ void __launch_bounds__(NTHR, 1)
lstm_persistent_kernel(const float* __restrict__ x,
                       const float* __restrict__ h0,
                       const float* __restrict__ c0,
                       const float* __restrict__ w_ih,
                       const float* __restrict__ w_hh,
                       const float* __restrict__ b_ih,
                       const float* __restrict__ b_hh,
                       float* __restrict__ out) {
    __shared__ float in_s[128 * 36];   // 128 rows x 32 k, padded stride 36
    __shared__ float w_s[64 * 36];     // 64 cols x 32 k

    const int tid = threadIdx.x;
    const int tx = tid & 15;           // 16 col-groups of 4
    const int ty = tid >> 4;           // 16 row-groups of 8
    const int ntile  = blockIdx.x & 31;   // 32 N-tiles of 64 cols
    const int ksplit = blockIdx.x >> 5;   // 4 K-splits of 256
    const bool is_x = (ksplit < 2);
    const int kb = (ksplit & 1) * 256;    // local k base within source

    // elementwise ownership: 2 (b,h) elements per thread, fixed across steps
    const int e_idx0 = blockIdx.x * 512 + tid * 2;
    const int eb0 = e_idx0 >> 9, eh0 = e_idx0 & 511;
    const int eb1 = (e_idx0 + 1) >> 9, eh1 = (e_idx0 + 1) & 511;

    for (int l = 0; l < L; ++l) {
        const float* wsrc = (is_x ? w_ih : w_hh) + (size_t)l * G * 512;
        const float* h0_l = h0 + (size_t)l * BH;
        const float* c0_l = c0 + (size_t)l * BH;

        // per-layer biases for owned elements (registers)
        float bias0[4], bias1[4];
        #pragma unroll
        for (int gq = 0; gq < 4; ++gq) {
            bias0[gq] = b_ih[(size_t)l * G + gq * H + eh0] + b_hh[(size_t)l * G + gq * H + eh0];
            bias1[gq] = b_ih[(size_t)l * G + gq * H + eh1] + b_hh[(size_t)l * G + gq * H + eh1];
        }
        float creg0 = 0.f, creg1 = 0.f;   // cell state carried in registers

        for (int t = 0; t < T; ++t) {
            // ---------------- GEMM partial: out(b, col) over this block's K range
            const float* src;
            int rs;
            bool src_is_seq;  // true -> must bypass L1 (written cross-SM)
            if (is_x) {
                if (l == 0) { src = x + (size_t)t * NI; rs = T * NI; src_is_seq = false; }
                else        { src = g_seq + (size_t)t * BH; rs = H;  src_is_seq = true;  }
            } else {
                if (t == 0) { src = h0_l; rs = H; src_is_seq = false; }
                else        { src = g_seq + (size_t)(t - 1) * BH; rs = H; src_is_seq = true; }
            }

            float acc[8][4];
            #pragma unroll
            for (int r = 0; r < 8; ++r)
                #pragma unroll
                for (int c = 0; c < 4; ++c) acc[r][c] = 0.f;

            for (int ch = 0; ch < 8; ++ch) {
                const int k0 = kb + ch * 32;
                // stage input tile 128x32
                #pragma unroll
                for (int q = 0; q < 4; ++q) {
                    int idq = tid + q * NTHR;
                    int row = idq >> 3, quad = idq & 7;
                    const float4* gp = (const float4*)(src + (size_t)row * rs + k0 + quad * 4);
                    float4 v;
                    if (src_is_seq) {
                        v = __ldcg(gp);       // L2-only: cross-SM produced data
                    } else {
                        v = __ldg(gp);
                    }
                    *(float4*)&in_s[row * 36 + quad * 4] = v;
                }
                // stage weight tile 64x32
                #pragma unroll
                for (int q = 0; q < 2; ++q) {
                    int idq = tid + q * NTHR;
                    int wrow = idq >> 3, quad = idq & 7;
                    float4 v = __ldg((const float4*)(wsrc + (size_t)(ntile * 64 + wrow) * 512 + k0 + quad * 4));
                    *(float4*)&w_s[wrow * 36 + quad * 4] = v;
                }
                __syncthreads();
                #pragma unroll
                for (int kk = 0; kk < 32; ++kk) {
                    float a[8], wv[4];
                    #pragma unroll
                    for (int r = 0; r < 8; ++r) a[r] = in_s[(ty * 8 + r) * 36 + kk];
                    #pragma unroll
                    for (int c = 0; c < 4; ++c) wv[c] = w_s[(tx * 4 + c) * 36 + kk];
                    #pragma unroll
                    for (int r = 0; r < 8; ++r)
                        #pragma unroll
                        for (int c = 0; c < 4; ++c)
                            acc[r][c] = fmaf(a[r], wv[c], acc[r][c]);
                }
                __syncthreads();
            }
            // write partials (plain STG -> L2)
            {
                float* pp = g_part + (size_t)ksplit * BG + ntile * 64 + tx * 4;
                #pragma unroll
                for (int r = 0; r < 8; ++r) {
                    float4 v = make_float4(acc[r][0], acc[r][1], acc[r][2], acc[r][3]);
                    *(float4*)(pp + (size_t)(ty * 8 + r) * G) = v;
                }
            }
            gsync();

            // ---------------- elementwise: gates -> (c, h) for 2 owned elements
            {
                // element 0
                float vi = bias0[0], vf = bias0[1], vg = bias0[2], vo = bias0[3];
                #pragma unroll
                for (int s = 0; s < 4; ++s) {
                    const float* p = g_part + (size_t)s * BG + (size_t)eb0 * G;
                    vi += __ldcg(p + eh0);
                    vf += __ldcg(p + H + eh0);
                    vg += __ldcg(p + 2 * H + eh0);
                    vo += __ldcg(p + 3 * H + eh0);
                }
                float co = (t == 0) ? c0_l[eb0 * H + eh0] : creg0;
                float cn = fmaf(sigmoidf_fast(vf), co, sigmoidf_fast(vi) * tanhf(vg));
                creg0 = cn;
                g_seq[(size_t)t * BH + eb0 * H + eh0] = sigmoidf_fast(vo) * tanhf(cn);
                if (t == T - 1) out[(size_t)l * BH + eb0 * H + eh0] = cn;
            }
            {
                // element 1
                float vi = bias1[0], vf = bias1[1], vg = bias1[2], vo = bias1[3];
                #pragma unroll
                for (int s = 0; s < 4; ++s) {
                    const float* p = g_part + (size_t)s * BG + (size_t)eb1 * G;
                    vi += __ldcg(p + eh1);
                    vf += __ldcg(p + H + eh1);
                    vg += __ldcg(p + 2 * H + eh1);
                    vo += __ldcg(p + 3 * H + eh1);
                }
                float co = (t == 0) ? c0_l[eb1 * H + eh1] : creg1;
                float cn = fmaf(sigmoidf_fast(vf), co, sigmoidf_fast(vi) * tanhf(vg));
                creg1 = cn;
                g_seq[(size_t)t * BH + eb1 * H + eh1] = sigmoidf_fast(vo) * tanhf(cn);
                if (t == T - 1) out[(size_t)l * BH + eb1 * H + eh1] = cn;
            }
            gsync();   // h(t) visible before GEMM(t+1) / next layer reads
        }
    }
}

extern "C" void kernel_launch(void* const* d_in, const int* in_sizes, int n_in,
                              void* d_out, int out_size) {
    const float* x    = (const float*)d_in[0];
    const float* h0   = (const float*)d_in[1];
    const float* c0   = (const float*)d_in[2];
    const float* w_ih = (const float*)d_in[3];
    const float* w_hh = (const float*)d_in[4];
    const float* b_ih = (const float*)d_in[5];
    const float* b_hh = (const float*)d_in[6];
    float* out = (float*)d_out;

    lstm_persistent_kernel<<<NBLK, NTHR>>>(x, h0, c0, w_ih, w_hh, b_ih, b_hh, out);
}